// round 8
// baseline (speedup 1.0000x reference)
#include <cuda_runtime.h>

// Fold (col2im): x (8, 32, 8, 8, 4096) f32, kernel (8,8), stride (4,4),
// n = 64 -> out (8, 32, 260, 260) f32.
//
// v4 = v3 (branch-free vector gather, shfl for the shifted element, fused
// tail in lane 15) + __launch_bounds__(256, 6):
//   v3 let ptxas batch all 16 LDG.128 (72 regs -> 3 CTAs/SM, occ 31.6%).
//   MLP was ~6x more than needed to hide DRAM latency; capping regs at ~42
//   trades surplus per-warp MLP for 2.3x more concurrent warps -> more
//   independent request streams at the memory controller.

#define LDIM 4096
#define H_   260
#define W_   260

__global__ __launch_bounds__(256, 6) void fold_v4_kernel(
    const float* __restrict__ x, float* __restrict__ out)
{
    const int idx = blockIdx.x * 256 + threadIdx.x;   // grid exactly covers TOTAL
    const int g  = idx & 15;
    const int t  = idx >> 4;
    const int h  = t % H_;
    const int bc = t / H_;

    const int r1 = h & 3;
    const int q1 = h >> 2;

    const float sA  = (q1 < 64) ? 1.f : 0.f;   // h-branch A valid
    const float sB  = (q1 >= 1) ? 1.f : 0.f;   // h-branch B valid
    const float sP  = (g > 0)   ? 1.f : 0.f;   // prev (wq>=1) valid
    const float sAP = sA * sP;
    const float sBP = sB * sP;

    const float* baseA = x + (size_t)(bc * 8 + r1)     * 8 * LDIM + q1 * 64 + 4 * g;
    const float* baseB = x + (size_t)(bc * 8 + r1 + 4) * 8 * LDIM + (q1 - 1) * 64 + 4 * g;

    float acc[16];
    #pragma unroll
    for (int i = 0; i < 16; i++) acc[i] = 0.f;
    float tl[4] = {0.f, 0.f, 0.f, 0.f};

    // ---- h-branch A: di = r1, p1 = q1 ----
    #pragma unroll
    for (int r = 0; r < 4; r++) {                 // dj = 0..3 (w-branch A)
        float4 a = __ldcs(reinterpret_cast<const float4*>(baseA + r * LDIM));
        acc[r]      += sA * a.x;  acc[4 + r]  += sA * a.y;
        acc[8 + r]  += sA * a.z;  acc[12 + r] += sA * a.w;
    }
    #pragma unroll
    for (int r = 0; r < 4; r++) {                 // dj = 4..7 (w-branch B)
        float4 b = __ldcs(reinterpret_cast<const float4*>(baseA + (r + 4) * LDIM));
        float prev = __shfl_up_sync(0xffffffffu, b.w, 1, 16);
        acc[r]      += sAP * prev; acc[4 + r]  += sA * b.x;
        acc[8 + r]  += sA * b.y;   acc[12 + r] += sA * b.z;
        tl[r]       += sA * b.w;                  // tail (only lane 15 stores)
    }

    // ---- h-branch B: di = r1 + 4, p1 = q1 - 1 ----
    #pragma unroll
    for (int r = 0; r < 4; r++) {
        float4 a = __ldcs(reinterpret_cast<const float4*>(baseB + r * LDIM));
        acc[r]      += sB * a.x;  acc[4 + r]  += sB * a.y;
        acc[8 + r]  += sB * a.z;  acc[12 + r] += sB * a.w;
    }
    #pragma unroll
    for (int r = 0; r < 4; r++) {
        float4 b = __ldcs(reinterpret_cast<const float4*>(baseB + (r + 4) * LDIM));
        float prev = __shfl_up_sync(0xffffffffu, b.w, 1, 16);
        acc[r]      += sBP * prev; acc[4 + r]  += sB * b.x;
        acc[8 + r]  += sB * b.y;   acc[12 + r] += sB * b.z;
        tl[r]       += sB * b.w;
    }

    float* o = out + ((size_t)bc * H_ + h) * W_ + 16 * g;
    #pragma unroll
    for (int j = 0; j < 4; j++)
        __stcs(reinterpret_cast<float4*>(o + 4 * j),
               make_float4(acc[4 * j + 0], acc[4 * j + 1],
                           acc[4 * j + 2], acc[4 * j + 3]));
    if (g == 15)
        __stcs(reinterpret_cast<float4*>(o + 16),     // w = 256..259
               make_float4(tl[0], tl[1], tl[2], tl[3]));
}

extern "C" void kernel_launch(void* const* d_in, const int* in_sizes, int n_in,
                              void* d_out, int out_size)
{
    const float* x = (const float*)d_in[0];
    float* out = (float*)d_out;
    // TOTAL = 256 (bc) * 260 (h) * 16 (g) = 1,064,960 = 4160 * 256 exactly.
    fold_v4_kernel<<<4160, 256>>>(x, out);
}